// round 3
// baseline (speedup 1.0000x reference)
#include <cuda_runtime.h>
#include <math.h>
#include <stdint.h>

// ---------------------------------------------------------------------------
// SpatioTemporalAttention: N=8, L=4096, C=1024, H=16, DH=64
//   queries = x_q @ Wq + bq
//   q_w     = softmax_L((queries @ Wqa + bqa) * 1/sqrt(DH))      per (n,h)
//   pooled_q[n,c] = sum_l q_w[n,h(c),l] * queries[n,l,c]
//   keys    = x_kv @ Wk + bk
//   k_w     = softmax_L(((keys * pooled_q) @ Wka + bka) / sqrt(DH))
//   pooled_k[n,c] = sum_l k_w[n,h(c),l] * keys[n,l,c]
//   tsum    = (values(=x_kv@Wv+bv) * pooled_k) @ Wt + bt + queries
//   out     = tsum @ Wp + bp
// ---------------------------------------------------------------------------

#define NB   8
#define LL   4096
#define CC   1024
#define HH   16
#define DH   64
#define MM   (NB*LL)      // 32768

// scratch (device globals; no runtime allocation allowed)
__device__ float g_queries[MM*CC];
__device__ float g_keys   [MM*CC];
__device__ float g_values [MM*CC];
__device__ float g_tsum   [MM*CC];
__device__ float g_logits [MM*HH];
__device__ float g_pq     [NB*CC];
__device__ float g_pk     [NB*CC];

__device__ __forceinline__ unsigned f2tf32(float x) {
    unsigned r;
    asm("cvt.rna.tf32.f32 %0, %1;" : "=r"(r) : "f"(x));
    return r;
}

__device__ __forceinline__ void mma_tf32(float c[4], const unsigned a[4], const unsigned b[2]) {
    asm volatile(
        "mma.sync.aligned.m16n8k8.row.col.f32.tf32.tf32.f32 "
        "{%0,%1,%2,%3}, {%4,%5,%6,%7}, {%8,%9}, {%0,%1,%2,%3};\n"
        : "+f"(c[0]), "+f"(c[1]), "+f"(c[2]), "+f"(c[3])
        : "r"(a[0]), "r"(a[1]), "r"(a[2]), "r"(a[3]), "r"(b[0]), "r"(b[1]));
}

// ---------------------------------------------------------------------------
// GEMM: out[M,1024] = (A .* gate?) @ W[1024,1024] + bias (+ addm)
// BM=128 BN=128 BK=32, 256 threads (8 warps, 2x4), warp tile 64x32,
// mma m16n8k8 tf32.
// gate: per (batch, k-channel) scalar applied to A on load (GATE).
// addm: elementwise matrix added in epilogue (ADD).
// ---------------------------------------------------------------------------
template<bool GATE, bool ADD>
__global__ void __launch_bounds__(256, 2) gemm_tf32_kernel(
    const float* __restrict__ A, const float* __restrict__ W,
    const float* __restrict__ bias, const float* __restrict__ gate,
    const float* __restrict__ addm, float* __restrict__ out)
{
    __shared__ unsigned As[128 * 36];   // stride 36 (16B-aligned rows, pad)
    __shared__ unsigned Bs[32 * 132];   // [k][n] stride 132

    const int tid  = threadIdx.x;
    const int bm   = blockIdx.y;
    const int bn   = blockIdx.x;
    const int warp = tid >> 5;
    const int lane = tid & 31;
    const int wm   = warp >> 2;     // 0..1
    const int wn   = warp & 3;      // 0..3
    const int nb   = (bm * 128) / LL;  // batch index (constant per block)

    float acc[4][4][4];
#pragma unroll
    for (int i = 0; i < 4; i++)
#pragma unroll
        for (int j = 0; j < 4; j++)
#pragma unroll
            for (int r = 0; r < 4; r++) acc[i][j][r] = 0.f;

    const int a_row0 = tid >> 3;           // + 32*i
    const int a_c4   = (tid & 7) * 4;
    const int b_kr0  = tid >> 5;           // + 8*i
    const int b_c4   = (tid & 31) * 4;

    for (int kb = 0; kb < CC; kb += 32) {
        // ---- load A tile [128 x 32] ----
#pragma unroll
        for (int i = 0; i < 4; i++) {
            const int r = a_row0 + 32 * i;
            float4 v = *(const float4*)(A + (size_t)(bm * 128 + r) * CC + kb + a_c4);
            if (GATE) {
                const float4 g = *(const float4*)(gate + nb * CC + kb + a_c4);
                v.x *= g.x; v.y *= g.y; v.z *= g.z; v.w *= g.w;
            }
            unsigned* p = &As[r * 36 + a_c4];
            p[0] = f2tf32(v.x); p[1] = f2tf32(v.y);
            p[2] = f2tf32(v.z); p[3] = f2tf32(v.w);
        }
        // ---- load B tile [32 x 128] ----
#pragma unroll
        for (int i = 0; i < 4; i++) {
            const int kr = b_kr0 + 8 * i;
            const float4 v = *(const float4*)(W + (size_t)(kb + kr) * CC + bn * 128 + b_c4);
            unsigned* p = &Bs[kr * 132 + b_c4];
            p[0] = f2tf32(v.x); p[1] = f2tf32(v.y);
            p[2] = f2tf32(v.z); p[3] = f2tf32(v.w);
        }
        __syncthreads();

#pragma unroll
        for (int ks = 0; ks < 4; ks++) {
            const int k0 = ks * 8;
            unsigned af[4][4], bf[4][2];
#pragma unroll
            for (int mt = 0; mt < 4; mt++) {
                const int row = wm * 64 + mt * 16 + (lane >> 2);
                const int col = k0 + (lane & 3);
                af[mt][0] = As[row * 36 + col];
                af[mt][1] = As[(row + 8) * 36 + col];
                af[mt][2] = As[row * 36 + col + 4];
                af[mt][3] = As[(row + 8) * 36 + col + 4];
            }
#pragma unroll
            for (int nt = 0; nt < 4; nt++) {
                const int coln = wn * 32 + nt * 8 + (lane >> 2);
                const int kk   = k0 + (lane & 3);
                bf[nt][0] = Bs[kk * 132 + coln];
                bf[nt][1] = Bs[(kk + 4) * 132 + coln];
            }
#pragma unroll
            for (int mt = 0; mt < 4; mt++)
#pragma unroll
                for (int nt = 0; nt < 4; nt++)
                    mma_tf32(acc[mt][nt], af[mt], bf[nt]);
        }
        __syncthreads();
    }

    // ---- epilogue ----
#pragma unroll
    for (int mt = 0; mt < 4; mt++) {
        const int r0 = bm * 128 + wm * 64 + mt * 16 + (lane >> 2);
#pragma unroll
        for (int nt = 0; nt < 4; nt++) {
            const int c0 = bn * 128 + wn * 32 + nt * 8 + (lane & 3) * 2;
            const float b0 = bias[c0], b1 = bias[c0 + 1];
            float v00 = acc[mt][nt][0] + b0;
            float v01 = acc[mt][nt][1] + b1;
            float v10 = acc[mt][nt][2] + b0;
            float v11 = acc[mt][nt][3] + b1;
            if (ADD) {
                v00 += addm[(size_t)r0 * CC + c0];
                v01 += addm[(size_t)r0 * CC + c0 + 1];
                v10 += addm[(size_t)(r0 + 8) * CC + c0];
                v11 += addm[(size_t)(r0 + 8) * CC + c0 + 1];
            }
            out[(size_t)r0 * CC + c0]           = v00;
            out[(size_t)r0 * CC + c0 + 1]       = v01;
            out[(size_t)(r0 + 8) * CC + c0]     = v10;
            out[(size_t)(r0 + 8) * CC + c0 + 1] = v11;
        }
    }
}

// ---------------------------------------------------------------------------
// logits[m, h] = ((X[m,:] .* gate?) @ Wa[:,h] + ba[h]) * 1/sqrt(DH)
// One warp per row, 8 warps per block.
// ---------------------------------------------------------------------------
template<bool GATE>
__global__ void logits_kernel(
    const float* __restrict__ X, const float* __restrict__ Wa,
    const float* __restrict__ ba, const float* __restrict__ gate,
    float* __restrict__ logits)
{
    const int warp = threadIdx.x >> 5;
    const int lane = threadIdx.x & 31;
    const int row  = blockIdx.x * 8 + warp;
    const int nb   = row / LL;

    float acc[HH];
#pragma unroll
    for (int h = 0; h < HH; h++) acc[h] = 0.f;

    for (int k = lane; k < CC; k += 32) {
        float xv = X[(size_t)row * CC + k];
        if (GATE) xv *= gate[nb * CC + k];
        const float4* wr = (const float4*)(Wa + (size_t)k * HH);
        const float4 w0 = wr[0], w1 = wr[1], w2 = wr[2], w3 = wr[3];
        acc[0]  += xv * w0.x; acc[1]  += xv * w0.y; acc[2]  += xv * w0.z; acc[3]  += xv * w0.w;
        acc[4]  += xv * w1.x; acc[5]  += xv * w1.y; acc[6]  += xv * w1.z; acc[7]  += xv * w1.w;
        acc[8]  += xv * w2.x; acc[9]  += xv * w2.y; acc[10] += xv * w2.z; acc[11] += xv * w2.w;
        acc[12] += xv * w3.x; acc[13] += xv * w3.y; acc[14] += xv * w3.z; acc[15] += xv * w3.w;
    }
#pragma unroll
    for (int h = 0; h < HH; h++) {
#pragma unroll
        for (int off = 16; off > 0; off >>= 1)
            acc[h] += __shfl_down_sync(0xffffffffu, acc[h], off);
    }
    if (lane == 0) {
        const float scale = 0.125f;  // 1/sqrt(64)
#pragma unroll
        for (int h = 0; h < HH; h++)
            logits[(size_t)row * HH + h] = (acc[h] + ba[h]) * scale;
    }
}

// ---------------------------------------------------------------------------
// Per (n,h): w = softmax_L(logits[n,:,h]);
//            pooled[n, h*64+d] = sum_l w[l] * X[n, l, h*64+d]
// One block per (n,h) pair; 256 threads.
// ---------------------------------------------------------------------------
__global__ void softmax_pool_kernel(
    const float* __restrict__ logits, const float* __restrict__ X,
    float* __restrict__ pooled)
{
    __shared__ float w[LL];
    __shared__ float red[256];

    const int n   = blockIdx.x >> 4;
    const int h   = blockIdx.x & 15;
    const int tid = threadIdx.x;

    float lmax = -INFINITY;
    for (int l = tid; l < LL; l += 256) {
        const float v = logits[(size_t)(n * LL + l) * HH + h];
        w[l] = v;
        lmax = fmaxf(lmax, v);
    }
    red[tid] = lmax;
    __syncthreads();
    for (int s = 128; s > 0; s >>= 1) {
        if (tid < s) red[tid] = fmaxf(red[tid], red[tid + s]);
        __syncthreads();
    }
    const float m = red[0];
    __syncthreads();

    float lsum = 0.f;
    for (int l = tid; l < LL; l += 256) {
        const float e = expf(w[l] - m);
        w[l] = e;
        lsum += e;
    }
    red[tid] = lsum;
    __syncthreads();
    for (int s = 128; s > 0; s >>= 1) {
        if (tid < s) red[tid] += red[tid + s];
        __syncthreads();
    }
    const float inv = 1.0f / red[0];
    __syncthreads();

    const int d = tid & 63;
    const int g = tid >> 6;     // 4 l-groups
    float acc = 0.f;
    for (int l = g; l < LL; l += 4)
        acc += w[l] * X[(size_t)(n * LL + l) * CC + h * DH + d];

    red[tid] = acc;
    __syncthreads();
    if (tid < 64)
        pooled[n * CC + h * DH + d] =
            (red[d] + red[64 + d] + red[128 + d] + red[192 + d]) * inv;
}

// ---------------------------------------------------------------------------
extern "C" void kernel_launch(void* const* d_in, const int* in_sizes, int n_in,
                              void* d_out, int out_size)
{
    const float* x_q  = (const float*)d_in[0];
    const float* x_kv = (const float*)d_in[1];
    const float* Wq   = (const float*)d_in[2];
    const float* bq   = (const float*)d_in[3];
    const float* Wqa  = (const float*)d_in[4];
    const float* bqa  = (const float*)d_in[5];
    const float* Wk   = (const float*)d_in[6];
    const float* bk   = (const float*)d_in[7];
    const float* Wka  = (const float*)d_in[8];
    const float* bka  = (const float*)d_in[9];
    const float* Wv   = (const float*)d_in[10];
    const float* bv   = (const float*)d_in[11];
    const float* Wt   = (const float*)d_in[12];
    const float* bt   = (const float*)d_in[13];
    const float* Wp   = (const float*)d_in[14];
    const float* bp   = (const float*)d_in[15];
    float* out = (float*)d_out;

    float *queries, *keys, *values, *tsum, *logits, *pq, *pk;
    cudaGetSymbolAddress((void**)&queries, g_queries);
    cudaGetSymbolAddress((void**)&keys,    g_keys);
    cudaGetSymbolAddress((void**)&values,  g_values);
    cudaGetSymbolAddress((void**)&tsum,    g_tsum);
    cudaGetSymbolAddress((void**)&logits,  g_logits);
    cudaGetSymbolAddress((void**)&pq,      g_pq);
    cudaGetSymbolAddress((void**)&pk,      g_pk);

    const dim3 ggrid(CC / 128, MM / 128);   // (8, 256)
    const dim3 gblk(256);

    // queries = x_q @ Wq + bq
    gemm_tf32_kernel<false, false><<<ggrid, gblk>>>(x_q, Wq, bq, nullptr, nullptr, queries);
    // q logits + softmax-pool -> pooled_q
    logits_kernel<false><<<MM / 8, 256>>>(queries, Wqa, bqa, nullptr, logits);
    softmax_pool_kernel<<<NB * HH, 256>>>(logits, queries, pq);
    // keys = x_kv @ Wk + bk
    gemm_tf32_kernel<false, false><<<ggrid, gblk>>>(x_kv, Wk, bk, nullptr, nullptr, keys);
    // k logits (keys gated by pooled_q) + softmax-pool -> pooled_k
    logits_kernel<true><<<MM / 8, 256>>>(keys, Wka, bka, pq, logits);
    softmax_pool_kernel<<<NB * HH, 256>>>(logits, keys, pk);
    // values = x_kv @ Wv + bv
    gemm_tf32_kernel<false, false><<<ggrid, gblk>>>(x_kv, Wv, bv, nullptr, nullptr, values);
    // tsum = (values .* pooled_k) @ Wt + bt + queries
    gemm_tf32_kernel<true, true><<<ggrid, gblk>>>(values, Wt, bt, pk, queries, tsum);
    // out = tsum @ Wp + bp
    gemm_tf32_kernel<false, false><<<ggrid, gblk>>>(tsum, Wp, bp, nullptr, nullptr, out);
}

// round 5
// speedup vs baseline: 1.1774x; 1.1774x over previous
#include <cuda_runtime.h>
#include <cuda_fp16.h>
#include <math.h>
#include <stdint.h>

// ---------------------------------------------------------------------------
// SpatioTemporalAttention  N=8 L=4096 C=1024 H=16 DH=64  (M = 32768)
// fp16 mma.sync (m16n8k16) + ldmatrix + cp.async double buffer.
// Note: harness ptxas targets plain sm_103 (no tcgen05).
// ---------------------------------------------------------------------------

#define NB   8
#define LL   4096
#define CC   1024
#define HH   16
#define DH   64
#define MM   (NB*LL)

#define BMH  128
#define BNH  128
#define BKH  64
#define KBH  (CC/BKH)          // 16
#define STAGE_B 32768          // A 16KB + B 16KB
#define SMEM_GEMM (2*STAGE_B)  // 64KB

// ---------------- scratch ----------------
__device__ __half g_xq_h  [MM*CC];
__device__ __half g_xkv_h [MM*CC];
__device__ __half g_valg_h[MM*CC];
__device__ __half g_tsum_h[MM*CC];
__device__ float  g_queries[MM*CC];
__device__ float  g_keys   [MM*CC];
__device__ __half g_WqT [CC*CC];
__device__ __half g_WkT [CC*CC];
__device__ __half g_WvT [CC*CC];
__device__ __half g_WtT [CC*CC];
__device__ __half g_WpT [CC*CC];
__device__ float  g_logits[MM*HH];
__device__ float  g_pq[NB*CC];
__device__ float  g_pk[NB*CC];

__device__ __forceinline__ uint32_t smem_u32(const void* p) {
    uint32_t a;
    asm("{ .reg .u64 t; cvta.to.shared.u64 t, %1; cvt.u32.u64 %0, t; }" : "=r"(a) : "l"(p));
    return a;
}
__device__ __forceinline__ void cp16(uint32_t s, const void* g) {
    asm volatile("cp.async.cg.shared.global [%0], [%1], 16;\n" :: "r"(s), "l"(g));
}
#define CP_COMMIT() asm volatile("cp.async.commit_group;\n" ::: "memory")
#define CP_WAIT1()  asm volatile("cp.async.wait_group 1;\n" ::: "memory")

__device__ __forceinline__ void ldsm4(uint32_t& r0, uint32_t& r1, uint32_t& r2,
                                      uint32_t& r3, uint32_t a) {
    asm volatile("ldmatrix.sync.aligned.m8n8.x4.shared.b16 {%0,%1,%2,%3}, [%4];"
                 : "=r"(r0), "=r"(r1), "=r"(r2), "=r"(r3) : "r"(a));
}
__device__ __forceinline__ void mma_f16(float c[4], const uint32_t a[4], const uint32_t b[2]) {
    asm volatile(
        "mma.sync.aligned.m16n8k16.row.col.f32.f16.f16.f32 "
        "{%0,%1,%2,%3}, {%4,%5,%6,%7}, {%8,%9}, {%0,%1,%2,%3};\n"
        : "+f"(c[0]), "+f"(c[1]), "+f"(c[2]), "+f"(c[3])
        : "r"(a[0]), "r"(a[1]), "r"(a[2]), "r"(a[3]), "r"(b[0]), "r"(b[1]));
}

// ---------------------------------------------------------------------------
// fp16 GEMM: out[bm,bn tiles] = A(half,[M,C]) @ B(half,[N,C])^T + bias
//   GATE: multiply (acc+bias) by gate[batch, col]   (values gating)
//   ADD : add float addm elementwise               (residual)
//   HOUT: write half output, else float
// 256 threads, 8 warps (2x4), warp tile 64x32, BK=64, 2-stage cp.async.
// ---------------------------------------------------------------------------
template<bool GATE, bool ADD, bool HOUT>
__global__ void __launch_bounds__(256, 2) gemm_h(
    const __half* __restrict__ A, const __half* __restrict__ Bm,
    const float* __restrict__ bias, const float* __restrict__ gate,
    const float* __restrict__ addm,
    float* __restrict__ outf, __half* __restrict__ outh)
{
    extern __shared__ __align__(128) char smem[];
    const uint32_t sbase = smem_u32(smem);
    const int tid  = threadIdx.x;
    const int lane = tid & 31;
    const int warp = tid >> 5;
    const int wm   = warp >> 2;       // 0..1
    const int wn   = warp & 3;        // 0..3
    const int bm   = blockIdx.y;
    const int bn   = blockIdx.x;
    const int nb   = (bm * BMH) / LL;

    const __half* Arow = A  + (size_t)bm * BMH * CC;
    const __half* Brow = Bm + (size_t)bn * BNH * CC;

    float acc[4][4][4];
#pragma unroll
    for (int i = 0; i < 4; i++)
#pragma unroll
        for (int j = 0; j < 4; j++)
#pragma unroll
            for (int r = 0; r < 4; r++) acc[i][j][r] = 0.f;

    // loader: each thread owns one 128B row (A: tid<128, B: tid>=128)
    const int lrow = tid & 127;
    const int isB  = tid >> 7;
    const __half* gsrc = isB ? Brow : Arow;
    const uint32_t doff = (uint32_t)isB * 16384 + (uint32_t)lrow * 128;
    const uint32_t xr   = (uint32_t)(lrow & 7) << 4;

#define LOAD_STAGE(stage, kb) do { \
        const char* g = (const char*)(gsrc + (size_t)lrow * CC + (kb) * BKH); \
        const uint32_t d = sbase + (stage) * STAGE_B + doff; \
        _Pragma("unroll") \
        for (int c = 0; c < 8; c++) \
            cp16(d + (((uint32_t)(c * 16)) ^ xr), g + c * 16); \
    } while (0)

    LOAD_STAGE(0, 0);
    CP_COMMIT();

#pragma unroll 1
    for (int kb = 0; kb < KBH; kb++) {
        if (kb + 1 < KBH) LOAD_STAGE((kb + 1) & 1, kb + 1);
        CP_COMMIT();
        CP_WAIT1();
        __syncthreads();

        const uint32_t sA = sbase + (kb & 1) * STAGE_B;
        const uint32_t sB = sA + 16384;
#pragma unroll
        for (int ks = 0; ks < 4; ks++) {
            const uint32_t kseg = (uint32_t)(ks * 32 + ((lane >> 4) * 16));
            uint32_t a_regs[4][4];
#pragma unroll
            for (int mt = 0; mt < 4; mt++) {
                const int row = wm * 64 + mt * 16 + (lane & 15);
                const uint32_t addr = sA + row * 128 + (kseg ^ ((uint32_t)(row & 7) << 4));
                ldsm4(a_regs[mt][0], a_regs[mt][1], a_regs[mt][2], a_regs[mt][3], addr);
            }
            uint32_t b_regs[4][2];
#pragma unroll
            for (int np = 0; np < 2; np++) {
                const int rowb = wn * 32 + np * 16 + (lane & 15);
                const uint32_t addr = sB + rowb * 128 + (kseg ^ ((uint32_t)(rowb & 7) << 4));
                uint32_t r0, r1, r2, r3;
                ldsm4(r0, r1, r2, r3, addr);
                b_regs[np * 2][0]     = r0;
                b_regs[np * 2 + 1][0] = r1;
                b_regs[np * 2][1]     = r2;
                b_regs[np * 2 + 1][1] = r3;
            }
#pragma unroll
            for (int mt = 0; mt < 4; mt++)
#pragma unroll
                for (int nt = 0; nt < 4; nt++)
                    mma_f16(acc[mt][nt], a_regs[mt], b_regs[nt]);
        }
        __syncthreads();
    }
#undef LOAD_STAGE

    // ---- epilogue ----
#pragma unroll
    for (int mt = 0; mt < 4; mt++) {
        const int r0 = bm * BMH + wm * 64 + mt * 16 + (lane >> 2);
#pragma unroll
        for (int nt = 0; nt < 4; nt++) {
            const int c0 = bn * BNH + wn * 32 + nt * 8 + (lane & 3) * 2;
            const float b0 = bias[c0], b1 = bias[c0 + 1];
            float v00 = acc[mt][nt][0] + b0;
            float v01 = acc[mt][nt][1] + b1;
            float v10 = acc[mt][nt][2] + b0;
            float v11 = acc[mt][nt][3] + b1;
            if (GATE) {
                const float gg0 = gate[nb * CC + c0], gg1 = gate[nb * CC + c0 + 1];
                v00 *= gg0; v01 *= gg1; v10 *= gg0; v11 *= gg1;
            }
            if (ADD) {
                v00 += addm[(size_t)r0 * CC + c0];
                v01 += addm[(size_t)r0 * CC + c0 + 1];
                v10 += addm[(size_t)(r0 + 8) * CC + c0];
                v11 += addm[(size_t)(r0 + 8) * CC + c0 + 1];
            }
            if (HOUT) {
                *(__half2*)(outh + (size_t)r0 * CC + c0)       = __floats2half2_rn(v00, v01);
                *(__half2*)(outh + (size_t)(r0 + 8) * CC + c0) = __floats2half2_rn(v10, v11);
            } else {
                outf[(size_t)r0 * CC + c0]           = v00;
                outf[(size_t)r0 * CC + c0 + 1]       = v01;
                outf[(size_t)(r0 + 8) * CC + c0]     = v10;
                outf[(size_t)(r0 + 8) * CC + c0 + 1] = v11;
            }
        }
    }
}

// ---------------- prep kernels ----------------
__global__ void f2h_kernel(const float* __restrict__ x, __half* __restrict__ y) {
    const size_t i = ((size_t)blockIdx.x * blockDim.x + threadIdx.x) * 4;
    const float4 v = *(const float4*)(x + i);
    *(__half2*)(y + i)     = __floats2half2_rn(v.x, v.y);
    *(__half2*)(y + i + 2) = __floats2half2_rn(v.z, v.w);
}

// dst[n][k] = (half) src[k][n]
__global__ void wtrans_h(const float* __restrict__ src, __half* __restrict__ dst) {
    __shared__ float t[32][33];
    const int bx = blockIdx.x * 32, by = blockIdx.y * 32;
    const int x = threadIdx.x, y = threadIdx.y;
#pragma unroll
    for (int j = 0; j < 32; j += 8)
        t[y + j][x] = src[(size_t)(by + y + j) * CC + bx + x];
    __syncthreads();
#pragma unroll
    for (int j = 0; j < 32; j += 8)
        dst[(size_t)(bx + y + j) * CC + by + x] = __float2half(t[x][y + j]);
}

// logits[m,h] = ((X[m,:] .* gate?) @ Wa[:,h] + ba[h]) / 8
template<bool GATE>
__global__ void logits_kernel(
    const float* __restrict__ X, const float* __restrict__ Wa,
    const float* __restrict__ ba, const float* __restrict__ gate,
    float* __restrict__ logits)
{
    const int warp = threadIdx.x >> 5;
    const int lane = threadIdx.x & 31;
    const int row  = blockIdx.x * 8 + warp;
    const int nb   = row / LL;

    float acc[HH];
#pragma unroll
    for (int h = 0; h < HH; h++) acc[h] = 0.f;

    for (int k = lane; k < CC; k += 32) {
        float xv = X[(size_t)row * CC + k];
        if (GATE) xv *= gate[nb * CC + k];
        const float4* wr = (const float4*)(Wa + (size_t)k * HH);
        const float4 w0 = wr[0], w1 = wr[1], w2 = wr[2], w3 = wr[3];
        acc[0]  += xv * w0.x; acc[1]  += xv * w0.y; acc[2]  += xv * w0.z; acc[3]  += xv * w0.w;
        acc[4]  += xv * w1.x; acc[5]  += xv * w1.y; acc[6]  += xv * w1.z; acc[7]  += xv * w1.w;
        acc[8]  += xv * w2.x; acc[9]  += xv * w2.y; acc[10] += xv * w2.z; acc[11] += xv * w2.w;
        acc[12] += xv * w3.x; acc[13] += xv * w3.y; acc[14] += xv * w3.z; acc[15] += xv * w3.w;
    }
#pragma unroll
    for (int h = 0; h < HH; h++) {
#pragma unroll
        for (int off = 16; off > 0; off >>= 1)
            acc[h] += __shfl_down_sync(0xffffffffu, acc[h], off);
    }
    if (lane == 0) {
        const float scale = 0.125f;
#pragma unroll
        for (int h = 0; h < HH; h++)
            logits[(size_t)row * HH + h] = (acc[h] + ba[h]) * scale;
    }
}

// per (n,h): w = softmax_L(logits[n,:,h]); pooled[n,h*64+d] = sum_l w[l]*X[n,l,h*64+d]
__global__ void softmax_pool_kernel(
    const float* __restrict__ logits, const float* __restrict__ X,
    float* __restrict__ pooled)
{
    __shared__ float w[LL];
    __shared__ float red[256];
    const int n   = blockIdx.x >> 4;
    const int h   = blockIdx.x & 15;
    const int tid = threadIdx.x;

    float lmax = -INFINITY;
    for (int l = tid; l < LL; l += 256) {
        const float v = logits[(size_t)(n * LL + l) * HH + h];
        w[l] = v;
        lmax = fmaxf(lmax, v);
    }
    red[tid] = lmax;
    __syncthreads();
    for (int s = 128; s > 0; s >>= 1) {
        if (tid < s) red[tid] = fmaxf(red[tid], red[tid + s]);
        __syncthreads();
    }
    const float m = red[0];
    __syncthreads();

    float lsum = 0.f;
    for (int l = tid; l < LL; l += 256) {
        const float e = expf(w[l] - m);
        w[l] = e;
        lsum += e;
    }
    red[tid] = lsum;
    __syncthreads();
    for (int s = 128; s > 0; s >>= 1) {
        if (tid < s) red[tid] += red[tid + s];
        __syncthreads();
    }
    const float inv = 1.0f / red[0];
    __syncthreads();

    const int d = tid & 63;
    const int g = tid >> 6;
    float acc = 0.f;
    for (int l = g; l < LL; l += 4)
        acc += w[l] * X[(size_t)(n * LL + l) * CC + h * DH + d];

    red[tid] = acc;
    __syncthreads();
    if (tid < 64)
        pooled[n * CC + h * DH + d] =
            (red[d] + red[64 + d] + red[128 + d] + red[192 + d]) * inv;
}

// ---------------------------------------------------------------------------
extern "C" void kernel_launch(void* const* d_in, const int* in_sizes, int n_in,
                              void* d_out, int out_size)
{
    const float* x_q  = (const float*)d_in[0];
    const float* x_kv = (const float*)d_in[1];
    const float* Wq   = (const float*)d_in[2];
    const float* bq   = (const float*)d_in[3];
    const float* Wqa  = (const float*)d_in[4];
    const float* bqa  = (const float*)d_in[5];
    const float* Wk   = (const float*)d_in[6];
    const float* bk   = (const float*)d_in[7];
    const float* Wka  = (const float*)d_in[8];
    const float* bka  = (const float*)d_in[9];
    const float* Wv   = (const float*)d_in[10];
    const float* bv   = (const float*)d_in[11];
    const float* Wt   = (const float*)d_in[12];
    const float* bt   = (const float*)d_in[13];
    const float* Wp   = (const float*)d_in[14];
    const float* bp   = (const float*)d_in[15];
    float* out = (float*)d_out;

    __half *xqh, *xkvh, *valgh, *tsumh, *WqT, *WkT, *WvT, *WtT, *WpT;
    float *queries, *keys, *logits, *pq, *pk;
    cudaGetSymbolAddress((void**)&xqh,     g_xq_h);
    cudaGetSymbolAddress((void**)&xkvh,    g_xkv_h);
    cudaGetSymbolAddress((void**)&valgh,   g_valg_h);
    cudaGetSymbolAddress((void**)&tsumh,   g_tsum_h);
    cudaGetSymbolAddress((void**)&queries, g_queries);
    cudaGetSymbolAddress((void**)&keys,    g_keys);
    cudaGetSymbolAddress((void**)&WqT,     g_WqT);
    cudaGetSymbolAddress((void**)&WkT,     g_WkT);
    cudaGetSymbolAddress((void**)&WvT,     g_WvT);
    cudaGetSymbolAddress((void**)&WtT,     g_WtT);
    cudaGetSymbolAddress((void**)&WpT,     g_WpT);
    cudaGetSymbolAddress((void**)&logits,  g_logits);
    cudaGetSymbolAddress((void**)&pq,      g_pq);
    cudaGetSymbolAddress((void**)&pk,      g_pk);

    cudaFuncSetAttribute(gemm_h<false,false,false>, cudaFuncAttributeMaxDynamicSharedMemorySize, SMEM_GEMM);
    cudaFuncSetAttribute(gemm_h<true, false,true >, cudaFuncAttributeMaxDynamicSharedMemorySize, SMEM_GEMM);
    cudaFuncSetAttribute(gemm_h<false,true, true >, cudaFuncAttributeMaxDynamicSharedMemorySize, SMEM_GEMM);

    const dim3 ggrid(CC / BNH, MM / BMH);   // (8, 256)
    const dim3 tgrid(CC / 32, CC / 32), tblk(32, 8);

    // prep
    f2h_kernel<<<MM * CC / 4 / 256, 256>>>(x_q,  xqh);
    f2h_kernel<<<MM * CC / 4 / 256, 256>>>(x_kv, xkvh);
    wtrans_h<<<tgrid, tblk>>>(Wq, WqT);
    wtrans_h<<<tgrid, tblk>>>(Wk, WkT);
    wtrans_h<<<tgrid, tblk>>>(Wv, WvT);
    wtrans_h<<<tgrid, tblk>>>(Wt, WtT);
    wtrans_h<<<tgrid, tblk>>>(Wp, WpT);

    // queries = xq @ Wq + bq   (float out)
    gemm_h<false,false,false><<<ggrid, 256, SMEM_GEMM>>>(
        xqh, WqT, bq, nullptr, nullptr, queries, nullptr);
    // pooled_q
    logits_kernel<false><<<MM / 8, 256>>>(queries, Wqa, bqa, nullptr, logits);
    softmax_pool_kernel<<<NB * HH, 256>>>(logits, queries, pq);
    // keys = xkv @ Wk + bk   (float out)
    gemm_h<false,false,false><<<ggrid, 256, SMEM_GEMM>>>(
        xkvh, WkT, bk, nullptr, nullptr, keys, nullptr);
    // pooled_k (keys gated by pooled_q)
    logits_kernel<true><<<MM / 8, 256>>>(keys, Wka, bka, pq, logits);
    softmax_pool_kernel<<<NB * HH, 256>>>(logits, keys, pk);
    // gated values = (xkv @ Wv + bv) * pk  (half out)
    gemm_h<true,false,true><<<ggrid, 256, SMEM_GEMM>>>(
        xkvh, WvT, bv, pk, nullptr, nullptr, valgh);
    // tsum = valg @ Wt + bt + queries  (half out)
    gemm_h<false,true,true><<<ggrid, 256, SMEM_GEMM>>>(
        valgh, WtT, bt, nullptr, queries, nullptr, tsumh);
    // out = tsum @ Wp + bp  (float out)
    gemm_h<false,false,false><<<ggrid, 256, SMEM_GEMM>>>(
        tsumh, WpT, bp, nullptr, nullptr, out, nullptr);
}

// round 6
// speedup vs baseline: 1.4475x; 1.2295x over previous
#include <cuda_runtime.h>
#include <cuda_fp16.h>
#include <math.h>
#include <stdint.h>

// ---------------------------------------------------------------------------
// SpatioTemporalAttention  N=8 L=4096 C=1024 H=16 DH=64  (M = 32768)
// fp16 mma.sync m16n8k16 + ldmatrix + 3-stage cp.async; fused prep; smem-Wa
// logits; wide softmax-pool. (plain sm_103 target: no tcgen05.)
// ---------------------------------------------------------------------------

#define NB   8
#define LL   4096
#define CC   1024
#define HH   16
#define DH   64
#define MM   (NB*LL)

#define BMH  128
#define BNH  128
#define BKH  64
#define KBH  (CC/BKH)          // 16
#define STAGE_B 32768          // A 16KB + B 16KB
#define SMEM_GEMM (3*STAGE_B)  // 96KB

#define WA_STRIDE 20           // floats per Wa row in smem (16B aligned, odd 16B-chunk stride)
#define SMEM_LOGITS (CC*WA_STRIDE*4)   // 80KB

// ---------------- scratch ----------------
__device__ __half g_xq_h  [MM*CC];
__device__ __half g_xkv_h [MM*CC];
__device__ __half g_valg_h[MM*CC];
__device__ __half g_tsum_h[MM*CC];
__device__ float  g_queries[MM*CC];
__device__ float  g_keys   [MM*CC];
__device__ __half g_WqT [CC*CC];
__device__ __half g_WkT [CC*CC];
__device__ __half g_WvT [CC*CC];
__device__ __half g_WtT [CC*CC];
__device__ __half g_WpT [CC*CC];
__device__ float  g_logits[MM*HH];
__device__ float  g_pq[NB*CC];
__device__ float  g_pk[NB*CC];

__device__ __forceinline__ uint32_t smem_u32(const void* p) {
    uint32_t a;
    asm("{ .reg .u64 t; cvta.to.shared.u64 t, %1; cvt.u32.u64 %0, t; }" : "=r"(a) : "l"(p));
    return a;
}
__device__ __forceinline__ void cp16(uint32_t s, const void* g) {
    asm volatile("cp.async.cg.shared.global [%0], [%1], 16;\n" :: "r"(s), "l"(g));
}
#define CP_COMMIT() asm volatile("cp.async.commit_group;\n" ::: "memory")
#define CP_WAIT1()  asm volatile("cp.async.wait_group 1;\n" ::: "memory")

__device__ __forceinline__ void ldsm4(uint32_t& r0, uint32_t& r1, uint32_t& r2,
                                      uint32_t& r3, uint32_t a) {
    asm volatile("ldmatrix.sync.aligned.m8n8.x4.shared.b16 {%0,%1,%2,%3}, [%4];"
                 : "=r"(r0), "=r"(r1), "=r"(r2), "=r"(r3) : "r"(a));
}
__device__ __forceinline__ void mma_f16(float c[4], const uint32_t a[4], const uint32_t b[2]) {
    asm volatile(
        "mma.sync.aligned.m16n8k16.row.col.f32.f16.f16.f32 "
        "{%0,%1,%2,%3}, {%4,%5,%6,%7}, {%8,%9}, {%0,%1,%2,%3};\n"
        : "+f"(c[0]), "+f"(c[1]), "+f"(c[2]), "+f"(c[3])
        : "r"(a[0]), "r"(a[1]), "r"(a[2]), "r"(a[3]), "r"(b[0]), "r"(b[1]));
}

// ---------------------------------------------------------------------------
// fp16 GEMM, 3-stage cp.async pipeline, single sync/iter.
// ---------------------------------------------------------------------------
template<bool GATE, bool ADD, bool HOUT>
__global__ void __launch_bounds__(256, 2) gemm_h(
    const __half* __restrict__ A, const __half* __restrict__ Bm,
    const float* __restrict__ bias, const float* __restrict__ gate,
    const float* __restrict__ addm,
    float* __restrict__ outf, __half* __restrict__ outh)
{
    extern __shared__ __align__(128) char smem[];
    const uint32_t sbase = smem_u32(smem);
    const int tid  = threadIdx.x;
    const int lane = tid & 31;
    const int warp = tid >> 5;
    const int wm   = warp >> 2;
    const int wn   = warp & 3;
    const int bm   = blockIdx.y;
    const int bn   = blockIdx.x;
    const int nb   = (bm * BMH) / LL;

    const __half* Arow = A  + (size_t)bm * BMH * CC;
    const __half* Brow = Bm + (size_t)bn * BNH * CC;

    float acc[4][4][4];
#pragma unroll
    for (int i = 0; i < 4; i++)
#pragma unroll
        for (int j = 0; j < 4; j++)
#pragma unroll
            for (int r = 0; r < 4; r++) acc[i][j][r] = 0.f;

    const int lrow = tid & 127;
    const int isB  = tid >> 7;
    const __half* gsrc = isB ? Brow : Arow;
    const uint32_t doff = (uint32_t)isB * 16384 + (uint32_t)lrow * 128;
    const uint32_t xr   = (uint32_t)(lrow & 7) << 4;

#define LOAD_STAGE(stage, kb) do { \
        const char* g = (const char*)(gsrc + (size_t)lrow * CC + (kb) * BKH); \
        const uint32_t d = sbase + (stage) * STAGE_B + doff; \
        _Pragma("unroll") \
        for (int c = 0; c < 8; c++) \
            cp16(d + (((uint32_t)(c * 16)) ^ xr), g + c * 16); \
    } while (0)

    LOAD_STAGE(0, 0); CP_COMMIT();
    LOAD_STAGE(1, 1); CP_COMMIT();

#pragma unroll 1
    for (int kb = 0; kb < KBH; kb++) {
        CP_WAIT1();            // load kb complete
        __syncthreads();       // visible to all; prev-iter mma drained
        if (kb + 2 < KBH) {
            const int st = (kb + 2) % 3;
            LOAD_STAGE(st, kb + 2);
        }
        CP_COMMIT();           // (possibly empty group; keeps indices aligned)

        const uint32_t sA = sbase + (uint32_t)(kb % 3) * STAGE_B;
        const uint32_t sB = sA + 16384;
#pragma unroll
        for (int ks = 0; ks < 4; ks++) {
            const uint32_t kseg = (uint32_t)(ks * 32 + ((lane >> 4) * 16));
            uint32_t a_regs[4][4];
#pragma unroll
            for (int mt = 0; mt < 4; mt++) {
                const int row = wm * 64 + mt * 16 + (lane & 15);
                const uint32_t addr = sA + row * 128 + (kseg ^ ((uint32_t)(row & 7) << 4));
                ldsm4(a_regs[mt][0], a_regs[mt][1], a_regs[mt][2], a_regs[mt][3], addr);
            }
            uint32_t b_regs[4][2];
#pragma unroll
            for (int np = 0; np < 2; np++) {
                const int rowb = wn * 32 + np * 16 + (lane & 15);
                const uint32_t addr = sB + rowb * 128 + (kseg ^ ((uint32_t)(rowb & 7) << 4));
                uint32_t r0, r1, r2, r3;
                ldsm4(r0, r1, r2, r3, addr);
                b_regs[np * 2][0]     = r0;
                b_regs[np * 2 + 1][0] = r1;
                b_regs[np * 2][1]     = r2;
                b_regs[np * 2 + 1][1] = r3;
            }
#pragma unroll
            for (int mt = 0; mt < 4; mt++)
#pragma unroll
                for (int nt = 0; nt < 4; nt++)
                    mma_f16(acc[mt][nt], a_regs[mt], b_regs[nt]);
        }
    }
#undef LOAD_STAGE

    // ---- epilogue ----
#pragma unroll
    for (int mt = 0; mt < 4; mt++) {
        const int r0 = bm * BMH + wm * 64 + mt * 16 + (lane >> 2);
#pragma unroll
        for (int nt = 0; nt < 4; nt++) {
            const int c0 = bn * BNH + wn * 32 + nt * 8 + (lane & 3) * 2;
            const float b0 = bias[c0], b1 = bias[c0 + 1];
            float v00 = acc[mt][nt][0] + b0;
            float v01 = acc[mt][nt][1] + b1;
            float v10 = acc[mt][nt][2] + b0;
            float v11 = acc[mt][nt][3] + b1;
            if (GATE) {
                const float gg0 = gate[nb * CC + c0], gg1 = gate[nb * CC + c0 + 1];
                v00 *= gg0; v01 *= gg1; v10 *= gg0; v11 *= gg1;
            }
            if (ADD) {
                v00 += addm[(size_t)r0 * CC + c0];
                v01 += addm[(size_t)r0 * CC + c0 + 1];
                v10 += addm[(size_t)(r0 + 8) * CC + c0];
                v11 += addm[(size_t)(r0 + 8) * CC + c0 + 1];
            }
            if (HOUT) {
                *(__half2*)(outh + (size_t)r0 * CC + c0)       = __floats2half2_rn(v00, v01);
                *(__half2*)(outh + (size_t)(r0 + 8) * CC + c0) = __floats2half2_rn(v10, v11);
            } else {
                outf[(size_t)r0 * CC + c0]           = v00;
                outf[(size_t)r0 * CC + c0 + 1]       = v01;
                outf[(size_t)(r0 + 8) * CC + c0]     = v10;
                outf[(size_t)(r0 + 8) * CC + c0 + 1] = v11;
            }
        }
    }
}

// ---------------- prep kernels (fused launches) ----------------
__global__ void f2h_all(const float* __restrict__ xa, __half* __restrict__ ya,
                        const float* __restrict__ xb, __half* __restrict__ yb) {
    const float* x = blockIdx.y ? xb : xa;
    __half* y      = blockIdx.y ? yb : ya;
    const size_t i = ((size_t)blockIdx.x * blockDim.x + threadIdx.x) * 4;
    const float4 v = *(const float4*)(x + i);
    *(__half2*)(y + i)     = __floats2half2_rn(v.x, v.y);
    *(__half2*)(y + i + 2) = __floats2half2_rn(v.z, v.w);
}

__global__ void wtrans_all(
    const float* __restrict__ s0, const float* __restrict__ s1,
    const float* __restrict__ s2, const float* __restrict__ s3,
    const float* __restrict__ s4,
    __half* __restrict__ d0, __half* __restrict__ d1,
    __half* __restrict__ d2, __half* __restrict__ d3,
    __half* __restrict__ d4)
{
    __shared__ float t[32][33];
    const float* src; __half* dst;
    switch (blockIdx.z) {
        case 0: src = s0; dst = d0; break;
        case 1: src = s1; dst = d1; break;
        case 2: src = s2; dst = d2; break;
        case 3: src = s3; dst = d3; break;
        default: src = s4; dst = d4; break;
    }
    const int bx = blockIdx.x * 32, by = blockIdx.y * 32;
    const int x = threadIdx.x, y = threadIdx.y;
#pragma unroll
    for (int j = 0; j < 32; j += 8)
        t[y + j][x] = src[(size_t)(by + y + j) * CC + bx + x];
    __syncthreads();
#pragma unroll
    for (int j = 0; j < 32; j += 8)
        dst[(size_t)(bx + y + j) * CC + by + x] = __float2half(t[x][y + j]);
}

// ---------------------------------------------------------------------------
// logits v2: block = 128 rows, Wa (scaled, optionally gated) cached in smem.
// logits[m,h] = sum_k X[m,k] * Wa_s[k,h]  + ba[h]*0.125
// ---------------------------------------------------------------------------
template<bool GATE>
__global__ void __launch_bounds__(256) logits2_kernel(
    const float* __restrict__ X, const float* __restrict__ Wa,
    const float* __restrict__ ba, const float* __restrict__ gate,
    float* __restrict__ logits)
{
    extern __shared__ float Wa_s[];   // [1024][WA_STRIDE]
    const int tid  = threadIdx.x;
    const int warp = tid >> 5;
    const int lane = tid & 31;
    const int nbat = blockIdx.x >> 5;          // 32 blocks per batch

    for (int i = tid; i < CC * HH; i += 256) {
        const int k = i >> 4, h = i & 15;
        float v = Wa[i] * 0.125f;
        if (GATE) v *= gate[nbat * CC + k];
        Wa_s[k * WA_STRIDE + h] = v;
    }
    __syncthreads();

#pragma unroll 1
    for (int r = 0; r < 16; r++) {
        const int row = blockIdx.x * 128 + warp * 16 + r;
        const float* xrow = X + (size_t)row * CC;
        float acc[HH];
#pragma unroll
        for (int h = 0; h < HH; h++) acc[h] = 0.f;

#pragma unroll 4
        for (int jj = 0; jj < 32; jj++) {
            const int k = lane + 32 * jj;
            const float xv = xrow[k];
            const float* wr = Wa_s + k * WA_STRIDE;
            const float4 w0 = *(const float4*)(wr);
            const float4 w1 = *(const float4*)(wr + 4);
            const float4 w2 = *(const float4*)(wr + 8);
            const float4 w3 = *(const float4*)(wr + 12);
            acc[0]  += xv * w0.x; acc[1]  += xv * w0.y; acc[2]  += xv * w0.z; acc[3]  += xv * w0.w;
            acc[4]  += xv * w1.x; acc[5]  += xv * w1.y; acc[6]  += xv * w1.z; acc[7]  += xv * w1.w;
            acc[8]  += xv * w2.x; acc[9]  += xv * w2.y; acc[10] += xv * w2.z; acc[11] += xv * w2.w;
            acc[12] += xv * w3.x; acc[13] += xv * w3.y; acc[14] += xv * w3.z; acc[15] += xv * w3.w;
        }
#pragma unroll
        for (int h = 0; h < HH; h++) {
#pragma unroll
            for (int off = 16; off > 0; off >>= 1)
                acc[h] += __shfl_down_sync(0xffffffffu, acc[h], off);
        }
        if (lane == 0) {
#pragma unroll
            for (int h = 0; h < HH; h++)
                logits[(size_t)row * HH + h] = acc[h] + ba[h] * 0.125f;
        }
    }
}

// ---------------------------------------------------------------------------
// softmax+pool: 1024 threads per (n,h) block.
// ---------------------------------------------------------------------------
__global__ void __launch_bounds__(1024) softmax_pool_kernel(
    const float* __restrict__ logits, const float* __restrict__ X,
    float* __restrict__ pooled)
{
    __shared__ float w[LL];
    __shared__ float red[1024];
    const int n   = blockIdx.x >> 4;
    const int h   = blockIdx.x & 15;
    const int tid = threadIdx.x;

    float lmax = -INFINITY;
#pragma unroll
    for (int j = 0; j < 4; j++) {
        const int l = tid + j * 1024;
        const float v = logits[(size_t)(n * LL + l) * HH + h];
        w[l] = v;
        lmax = fmaxf(lmax, v);
    }
    red[tid] = lmax;
    __syncthreads();
    for (int s = 512; s > 0; s >>= 1) {
        if (tid < s) red[tid] = fmaxf(red[tid], red[tid + s]);
        __syncthreads();
    }
    const float m = red[0];
    __syncthreads();

    float lsum = 0.f;
#pragma unroll
    for (int j = 0; j < 4; j++) {
        const int l = tid + j * 1024;
        const float e = expf(w[l] - m);
        w[l] = e;
        lsum += e;
    }
    red[tid] = lsum;
    __syncthreads();
    for (int s = 512; s > 0; s >>= 1) {
        if (tid < s) red[tid] += red[tid + s];
        __syncthreads();
    }
    const float inv = 1.0f / red[0];
    __syncthreads();

    const int d = tid & 63;
    const int g = tid >> 6;     // 16 l-groups
    const float* xb = X + (size_t)n * LL * CC + h * DH + d;
    float acc = 0.f;
#pragma unroll 4
    for (int j = 0; j < 256; j++) {
        const int l = g + j * 16;
        acc += w[l] * xb[(size_t)l * CC];
    }
    red[tid] = acc;
    __syncthreads();
    if (tid < 64) {
        float s = 0.f;
#pragma unroll
        for (int gg = 0; gg < 16; gg++) s += red[gg * 64 + d];
        pooled[n * CC + h * DH + d] = s * inv;
    }
}

// ---------------------------------------------------------------------------
extern "C" void kernel_launch(void* const* d_in, const int* in_sizes, int n_in,
                              void* d_out, int out_size)
{
    const float* x_q  = (const float*)d_in[0];
    const float* x_kv = (const float*)d_in[1];
    const float* Wq   = (const float*)d_in[2];
    const float* bq   = (const float*)d_in[3];
    const float* Wqa  = (const float*)d_in[4];
    const float* bqa  = (const float*)d_in[5];
    const float* Wk   = (const float*)d_in[6];
    const float* bk   = (const float*)d_in[7];
    const float* Wka  = (const float*)d_in[8];
    const float* bka  = (const float*)d_in[9];
    const float* Wv   = (const float*)d_in[10];
    const float* bv   = (const float*)d_in[11];
    const float* Wt   = (const float*)d_in[12];
    const float* bt   = (const float*)d_in[13];
    const float* Wp   = (const float*)d_in[14];
    const float* bp   = (const float*)d_in[15];
    float* out = (float*)d_out;

    __half *xqh, *xkvh, *valgh, *tsumh, *WqT, *WkT, *WvT, *WtT, *WpT;
    float *queries, *keys, *logits, *pq, *pk;
    cudaGetSymbolAddress((void**)&xqh,     g_xq_h);
    cudaGetSymbolAddress((void**)&xkvh,    g_xkv_h);
    cudaGetSymbolAddress((void**)&valgh,   g_valg_h);
    cudaGetSymbolAddress((void**)&tsumh,   g_tsum_h);
    cudaGetSymbolAddress((void**)&queries, g_queries);
    cudaGetSymbolAddress((void**)&keys,    g_keys);
    cudaGetSymbolAddress((void**)&WqT,     g_WqT);
    cudaGetSymbolAddress((void**)&WkT,     g_WkT);
    cudaGetSymbolAddress((void**)&WvT,     g_WvT);
    cudaGetSymbolAddress((void**)&WtT,     g_WtT);
    cudaGetSymbolAddress((void**)&WpT,     g_WpT);
    cudaGetSymbolAddress((void**)&logits,  g_logits);
    cudaGetSymbolAddress((void**)&pq,      g_pq);
    cudaGetSymbolAddress((void**)&pk,      g_pk);

    cudaFuncSetAttribute(gemm_h<false,false,false>, cudaFuncAttributeMaxDynamicSharedMemorySize, SMEM_GEMM);
    cudaFuncSetAttribute(gemm_h<true, false,true >, cudaFuncAttributeMaxDynamicSharedMemorySize, SMEM_GEMM);
    cudaFuncSetAttribute(gemm_h<false,true, true >, cudaFuncAttributeMaxDynamicSharedMemorySize, SMEM_GEMM);
    cudaFuncSetAttribute(logits2_kernel<false>, cudaFuncAttributeMaxDynamicSharedMemorySize, SMEM_LOGITS);
    cudaFuncSetAttribute(logits2_kernel<true >, cudaFuncAttributeMaxDynamicSharedMemorySize, SMEM_LOGITS);

    const dim3 ggrid(CC / BNH, MM / BMH);   // (8, 256)
    const dim3 tgrid(CC / 32, CC / 32, 5), tblk(32, 8);

    // #1 convert both activations
    f2h_all<<<dim3(MM * CC / 4 / 256, 2), 256>>>(x_q, xqh, x_kv, xkvh);
    // #2 transpose all 5 weights
    wtrans_all<<<tgrid, tblk>>>(Wq, Wk, Wv, Wt, Wp, WqT, WkT, WvT, WtT, WpT);
    // #3 queries = xq @ Wq + bq  (f32)
    gemm_h<false,false,false><<<ggrid, 256, SMEM_GEMM>>>(
        xqh, WqT, bq, nullptr, nullptr, queries, nullptr);
    // #4,#5 pooled_q
    logits2_kernel<false><<<MM / 128, 256, SMEM_LOGITS>>>(queries, Wqa, bqa, nullptr, logits);
    softmax_pool_kernel<<<NB * HH, 1024>>>(logits, queries, pq);
    // #6 keys = xkv @ Wk + bk  (f32)  <- profiled launch
    gemm_h<false,false,false><<<ggrid, 256, SMEM_GEMM>>>(
        xkvh, WkT, bk, nullptr, nullptr, keys, nullptr);
    // #7,#8 pooled_k (keys gated by pooled_q, folded into Wa_s)
    logits2_kernel<true><<<MM / 128, 256, SMEM_LOGITS>>>(keys, Wka, bka, pq, logits);
    softmax_pool_kernel<<<NB * HH, 1024>>>(logits, keys, pk);
    // #9 gated values = (xkv @ Wv + bv) * pk  (half)
    gemm_h<true,false,true><<<ggrid, 256, SMEM_GEMM>>>(
        xkvh, WvT, bv, pk, nullptr, nullptr, valgh);
    // #10 tsum = valg @ Wt + bt + queries  (half)
    gemm_h<false,true,true><<<ggrid, 256, SMEM_GEMM>>>(
        valgh, WtT, bt, nullptr, queries, nullptr, tsumh);
    // #11 out = tsum @ Wp + bp  (f32)
    gemm_h<false,false,false><<<ggrid, 256, SMEM_GEMM>>>(
        tsumh, WpT, bp, nullptr, nullptr, out, nullptr);
}

// round 7
// speedup vs baseline: 1.4547x; 1.0050x over previous
#include <cuda_runtime.h>
#include <cuda_fp16.h>
#include <math.h>
#include <stdint.h>

// ---------------------------------------------------------------------------
// SpatioTemporalAttention  N=8 L=4096 C=1024 H=16 DH=64  (M = 32768)
// fp16 mma.sync m16n8k16 + ldmatrix + 3-stage cp.async; fused prep; smem-Wa
// logits; wide softmax-pool. (plain sm_103 target: no tcgen05.)
// ---------------------------------------------------------------------------

#define NB   8
#define LL   4096
#define CC   1024
#define HH   16
#define DH   64
#define MM   (NB*LL)

#define BMH  128
#define BNH  128
#define BKH  64
#define KBH  (CC/BKH)          // 16
#define STAGE_B 32768          // A 16KB + B 16KB
#define SMEM_GEMM (3*STAGE_B)  // 96KB

#define WA_STRIDE 20           // floats per Wa row in smem (16B aligned, odd 16B-chunk stride)
#define SMEM_LOGITS (CC*WA_STRIDE*4)   // 80KB

// ---------------- scratch ----------------
__device__ __half g_xq_h  [MM*CC];
__device__ __half g_xkv_h [MM*CC];
__device__ __half g_valg_h[MM*CC];
__device__ __half g_tsum_h[MM*CC];
__device__ float  g_queries[MM*CC];
__device__ float  g_keys   [MM*CC];
__device__ __half g_WqT [CC*CC];
__device__ __half g_WkT [CC*CC];
__device__ __half g_WvT [CC*CC];
__device__ __half g_WtT [CC*CC];
__device__ __half g_WpT [CC*CC];
__device__ float  g_logits[MM*HH];
__device__ float  g_pq[NB*CC];
__device__ float  g_pk[NB*CC];

__device__ __forceinline__ uint32_t smem_u32(const void* p) {
    uint32_t a;
    asm("{ .reg .u64 t; cvta.to.shared.u64 t, %1; cvt.u32.u64 %0, t; }" : "=r"(a) : "l"(p));
    return a;
}
__device__ __forceinline__ void cp16(uint32_t s, const void* g) {
    asm volatile("cp.async.cg.shared.global [%0], [%1], 16;\n" :: "r"(s), "l"(g));
}
#define CP_COMMIT() asm volatile("cp.async.commit_group;\n" ::: "memory")
#define CP_WAIT1()  asm volatile("cp.async.wait_group 1;\n" ::: "memory")

__device__ __forceinline__ void ldsm4(uint32_t& r0, uint32_t& r1, uint32_t& r2,
                                      uint32_t& r3, uint32_t a) {
    asm volatile("ldmatrix.sync.aligned.m8n8.x4.shared.b16 {%0,%1,%2,%3}, [%4];"
                 : "=r"(r0), "=r"(r1), "=r"(r2), "=r"(r3) : "r"(a));
}
__device__ __forceinline__ void mma_f16(float c[4], const uint32_t a[4], const uint32_t b[2]) {
    asm volatile(
        "mma.sync.aligned.m16n8k16.row.col.f32.f16.f16.f32 "
        "{%0,%1,%2,%3}, {%4,%5,%6,%7}, {%8,%9}, {%0,%1,%2,%3};\n"
        : "+f"(c[0]), "+f"(c[1]), "+f"(c[2]), "+f"(c[3])
        : "r"(a[0]), "r"(a[1]), "r"(a[2]), "r"(a[3]), "r"(b[0]), "r"(b[1]));
}

// ---------------------------------------------------------------------------
// fp16 GEMM, 3-stage cp.async pipeline, single sync/iter.
// ---------------------------------------------------------------------------
template<bool GATE, bool ADD, bool HOUT>
__global__ void __launch_bounds__(256, 2) gemm_h(
    const __half* __restrict__ A, const __half* __restrict__ Bm,
    const float* __restrict__ bias, const float* __restrict__ gate,
    const float* __restrict__ addm,
    float* __restrict__ outf, __half* __restrict__ outh)
{
    extern __shared__ __align__(128) char smem[];
    const uint32_t sbase = smem_u32(smem);
    const int tid  = threadIdx.x;
    const int lane = tid & 31;
    const int warp = tid >> 5;
    const int wm   = warp >> 2;
    const int wn   = warp & 3;
    const int bm   = blockIdx.y;
    const int bn   = blockIdx.x;
    const int nb   = (bm * BMH) / LL;

    const __half* Arow = A  + (size_t)bm * BMH * CC;
    const __half* Brow = Bm + (size_t)bn * BNH * CC;

    float acc[4][4][4];
#pragma unroll
    for (int i = 0; i < 4; i++)
#pragma unroll
        for (int j = 0; j < 4; j++)
#pragma unroll
            for (int r = 0; r < 4; r++) acc[i][j][r] = 0.f;

    const int lrow = tid & 127;
    const int isB  = tid >> 7;
    const __half* gsrc = isB ? Brow : Arow;
    const uint32_t doff = (uint32_t)isB * 16384 + (uint32_t)lrow * 128;
    const uint32_t xr   = (uint32_t)(lrow & 7) << 4;

#define LOAD_STAGE(stage, kb) do { \
        const char* g = (const char*)(gsrc + (size_t)lrow * CC + (kb) * BKH); \
        const uint32_t d = sbase + (stage) * STAGE_B + doff; \
        _Pragma("unroll") \
        for (int c = 0; c < 8; c++) \
            cp16(d + (((uint32_t)(c * 16)) ^ xr), g + c * 16); \
    } while (0)

    LOAD_STAGE(0, 0); CP_COMMIT();
    LOAD_STAGE(1, 1); CP_COMMIT();

#pragma unroll 1
    for (int kb = 0; kb < KBH; kb++) {
        CP_WAIT1();            // load kb complete
        __syncthreads();       // visible to all; prev-iter mma drained
        if (kb + 2 < KBH) {
            const int st = (kb + 2) % 3;
            LOAD_STAGE(st, kb + 2);
        }
        CP_COMMIT();           // (possibly empty group; keeps indices aligned)

        const uint32_t sA = sbase + (uint32_t)(kb % 3) * STAGE_B;
        const uint32_t sB = sA + 16384;
#pragma unroll
        for (int ks = 0; ks < 4; ks++) {
            const uint32_t kseg = (uint32_t)(ks * 32 + ((lane >> 4) * 16));
            uint32_t a_regs[4][4];
#pragma unroll
            for (int mt = 0; mt < 4; mt++) {
                const int row = wm * 64 + mt * 16 + (lane & 15);
                const uint32_t addr = sA + row * 128 + (kseg ^ ((uint32_t)(row & 7) << 4));
                ldsm4(a_regs[mt][0], a_regs[mt][1], a_regs[mt][2], a_regs[mt][3], addr);
            }
            uint32_t b_regs[4][2];
#pragma unroll
            for (int np = 0; np < 2; np++) {
                const int rowb = wn * 32 + np * 16 + (lane & 15);
                const uint32_t addr = sB + rowb * 128 + (kseg ^ ((uint32_t)(rowb & 7) << 4));
                uint32_t r0, r1, r2, r3;
                ldsm4(r0, r1, r2, r3, addr);
                b_regs[np * 2][0]     = r0;
                b_regs[np * 2 + 1][0] = r1;
                b_regs[np * 2][1]     = r2;
                b_regs[np * 2 + 1][1] = r3;
            }
#pragma unroll
            for (int mt = 0; mt < 4; mt++)
#pragma unroll
                for (int nt = 0; nt < 4; nt++)
                    mma_f16(acc[mt][nt], a_regs[mt], b_regs[nt]);
        }
    }
#undef LOAD_STAGE

    // ---- epilogue ----
#pragma unroll
    for (int mt = 0; mt < 4; mt++) {
        const int r0 = bm * BMH + wm * 64 + mt * 16 + (lane >> 2);
#pragma unroll
        for (int nt = 0; nt < 4; nt++) {
            const int c0 = bn * BNH + wn * 32 + nt * 8 + (lane & 3) * 2;
            const float b0 = bias[c0], b1 = bias[c0 + 1];
            float v00 = acc[mt][nt][0] + b0;
            float v01 = acc[mt][nt][1] + b1;
            float v10 = acc[mt][nt][2] + b0;
            float v11 = acc[mt][nt][3] + b1;
            if (GATE) {
                const float gg0 = gate[nb * CC + c0], gg1 = gate[nb * CC + c0 + 1];
                v00 *= gg0; v01 *= gg1; v10 *= gg0; v11 *= gg1;
            }
            if (ADD) {
                v00 += addm[(size_t)r0 * CC + c0];
                v01 += addm[(size_t)r0 * CC + c0 + 1];
                v10 += addm[(size_t)(r0 + 8) * CC + c0];
                v11 += addm[(size_t)(r0 + 8) * CC + c0 + 1];
            }
            if (HOUT) {
                *(__half2*)(outh + (size_t)r0 * CC + c0)       = __floats2half2_rn(v00, v01);
                *(__half2*)(outh + (size_t)(r0 + 8) * CC + c0) = __floats2half2_rn(v10, v11);
            } else {
                outf[(size_t)r0 * CC + c0]           = v00;
                outf[(size_t)r0 * CC + c0 + 1]       = v01;
                outf[(size_t)(r0 + 8) * CC + c0]     = v10;
                outf[(size_t)(r0 + 8) * CC + c0 + 1] = v11;
            }
        }
    }
}

// ---------------- prep kernels (fused launches) ----------------
__global__ void f2h_all(const float* __restrict__ xa, __half* __restrict__ ya,
                        const float* __restrict__ xb, __half* __restrict__ yb) {
    const float* x = blockIdx.y ? xb : xa;
    __half* y      = blockIdx.y ? yb : ya;
    const size_t i = ((size_t)blockIdx.x * blockDim.x + threadIdx.x) * 4;
    const float4 v = *(const float4*)(x + i);
    *(__half2*)(y + i)     = __floats2half2_rn(v.x, v.y);
    *(__half2*)(y + i + 2) = __floats2half2_rn(v.z, v.w);
}

__global__ void wtrans_all(
    const float* __restrict__ s0, const float* __restrict__ s1,
    const float* __restrict__ s2, const float* __restrict__ s3,
    const float* __restrict__ s4,
    __half* __restrict__ d0, __half* __restrict__ d1,
    __half* __restrict__ d2, __half* __restrict__ d3,
    __half* __restrict__ d4)
{
    __shared__ float t[32][33];
    const float* src; __half* dst;
    switch (blockIdx.z) {
        case 0: src = s0; dst = d0; break;
        case 1: src = s1; dst = d1; break;
        case 2: src = s2; dst = d2; break;
        case 3: src = s3; dst = d3; break;
        default: src = s4; dst = d4; break;
    }
    const int bx = blockIdx.x * 32, by = blockIdx.y * 32;
    const int x = threadIdx.x, y = threadIdx.y;
#pragma unroll
    for (int j = 0; j < 32; j += 8)
        t[y + j][x] = src[(size_t)(by + y + j) * CC + bx + x];
    __syncthreads();
#pragma unroll
    for (int j = 0; j < 32; j += 8)
        dst[(size_t)(bx + y + j) * CC + by + x] = __float2half(t[x][y + j]);
}

// ---------------------------------------------------------------------------
// logits v2: block = 128 rows, Wa (scaled, optionally gated) cached in smem.
// logits[m,h] = sum_k X[m,k] * Wa_s[k,h]  + ba[h]*0.125
// ---------------------------------------------------------------------------
template<bool GATE>
__global__ void __launch_bounds__(256) logits2_kernel(
    const float* __restrict__ X, const float* __restrict__ Wa,
    const float* __restrict__ ba, const float* __restrict__ gate,
    float* __restrict__ logits)
{
    extern __shared__ float Wa_s[];   // [1024][WA_STRIDE]
    const int tid  = threadIdx.x;
    const int warp = tid >> 5;
    const int lane = tid & 31;
    const int nbat = blockIdx.x >> 5;          // 32 blocks per batch

    for (int i = tid; i < CC * HH; i += 256) {
        const int k = i >> 4, h = i & 15;
        float v = Wa[i] * 0.125f;
        if (GATE) v *= gate[nbat * CC + k];
        Wa_s[k * WA_STRIDE + h] = v;
    }
    __syncthreads();

#pragma unroll 1
    for (int r = 0; r < 16; r++) {
        const int row = blockIdx.x * 128 + warp * 16 + r;
        const float* xrow = X + (size_t)row * CC;
        float acc[HH];
#pragma unroll
        for (int h = 0; h < HH; h++) acc[h] = 0.f;

#pragma unroll 4
        for (int jj = 0; jj < 32; jj++) {
            const int k = lane + 32 * jj;
            const float xv = xrow[k];
            const float* wr = Wa_s + k * WA_STRIDE;
            const float4 w0 = *(const float4*)(wr);
            const float4 w1 = *(const float4*)(wr + 4);
            const float4 w2 = *(const float4*)(wr + 8);
            const float4 w3 = *(const float4*)(wr + 12);
            acc[0]  += xv * w0.x; acc[1]  += xv * w0.y; acc[2]  += xv * w0.z; acc[3]  += xv * w0.w;
            acc[4]  += xv * w1.x; acc[5]  += xv * w1.y; acc[6]  += xv * w1.z; acc[7]  += xv * w1.w;
            acc[8]  += xv * w2.x; acc[9]  += xv * w2.y; acc[10] += xv * w2.z; acc[11] += xv * w2.w;
            acc[12] += xv * w3.x; acc[13] += xv * w3.y; acc[14] += xv * w3.z; acc[15] += xv * w3.w;
        }
#pragma unroll
        for (int h = 0; h < HH; h++) {
#pragma unroll
            for (int off = 16; off > 0; off >>= 1)
                acc[h] += __shfl_down_sync(0xffffffffu, acc[h], off);
        }
        if (lane == 0) {
#pragma unroll
            for (int h = 0; h < HH; h++)
                logits[(size_t)row * HH + h] = acc[h] + ba[h] * 0.125f;
        }
    }
}

// ---------------------------------------------------------------------------
// softmax+pool: 1024 threads per (n,h) block.
// ---------------------------------------------------------------------------
__global__ void __launch_bounds__(1024) softmax_pool_kernel(
    const float* __restrict__ logits, const float* __restrict__ X,
    float* __restrict__ pooled)
{
    __shared__ float w[LL];
    __shared__ float red[1024];
    const int n   = blockIdx.x >> 4;
    const int h   = blockIdx.x & 15;
    const int tid = threadIdx.x;

    float lmax = -INFINITY;
#pragma unroll
    for (int j = 0; j < 4; j++) {
        const int l = tid + j * 1024;
        const float v = logits[(size_t)(n * LL + l) * HH + h];
        w[l] = v;
        lmax = fmaxf(lmax, v);
    }
    red[tid] = lmax;
    __syncthreads();
    for (int s = 512; s > 0; s >>= 1) {
        if (tid < s) red[tid] = fmaxf(red[tid], red[tid + s]);
        __syncthreads();
    }
    const float m = red[0];
    __syncthreads();

    float lsum = 0.f;
#pragma unroll
    for (int j = 0; j < 4; j++) {
        const int l = tid + j * 1024;
        const float e = expf(w[l] - m);
        w[l] = e;
        lsum += e;
    }
    red[tid] = lsum;
    __syncthreads();
    for (int s = 512; s > 0; s >>= 1) {
        if (tid < s) red[tid] += red[tid + s];
        __syncthreads();
    }
    const float inv = 1.0f / red[0];
    __syncthreads();

    const int d = tid & 63;
    const int g = tid >> 6;     // 16 l-groups
    const float* xb = X + (size_t)n * LL * CC + h * DH + d;
    float acc = 0.f;
#pragma unroll 4
    for (int j = 0; j < 256; j++) {
        const int l = g + j * 16;
        acc += w[l] * xb[(size_t)l * CC];
    }
    red[tid] = acc;
    __syncthreads();
    if (tid < 64) {
        float s = 0.f;
#pragma unroll
        for (int gg = 0; gg < 16; gg++) s += red[gg * 64 + d];
        pooled[n * CC + h * DH + d] = s * inv;
    }
}

// ---------------------------------------------------------------------------
extern "C" void kernel_launch(void* const* d_in, const int* in_sizes, int n_in,
                              void* d_out, int out_size)
{
    const float* x_q  = (const float*)d_in[0];
    const float* x_kv = (const float*)d_in[1];
    const float* Wq   = (const float*)d_in[2];
    const float* bq   = (const float*)d_in[3];
    const float* Wqa  = (const float*)d_in[4];
    const float* bqa  = (const float*)d_in[5];
    const float* Wk   = (const float*)d_in[6];
    const float* bk   = (const float*)d_in[7];
    const float* Wka  = (const float*)d_in[8];
    const float* bka  = (const float*)d_in[9];
    const float* Wv   = (const float*)d_in[10];
    const float* bv   = (const float*)d_in[11];
    const float* Wt   = (const float*)d_in[12];
    const float* bt   = (const float*)d_in[13];
    const float* Wp   = (const float*)d_in[14];
    const float* bp   = (const float*)d_in[15];
    float* out = (float*)d_out;

    __half *xqh, *xkvh, *valgh, *tsumh, *WqT, *WkT, *WvT, *WtT, *WpT;
    float *queries, *keys, *logits, *pq, *pk;
    cudaGetSymbolAddress((void**)&xqh,     g_xq_h);
    cudaGetSymbolAddress((void**)&xkvh,    g_xkv_h);
    cudaGetSymbolAddress((void**)&valgh,   g_valg_h);
    cudaGetSymbolAddress((void**)&tsumh,   g_tsum_h);
    cudaGetSymbolAddress((void**)&queries, g_queries);
    cudaGetSymbolAddress((void**)&keys,    g_keys);
    cudaGetSymbolAddress((void**)&WqT,     g_WqT);
    cudaGetSymbolAddress((void**)&WkT,     g_WkT);
    cudaGetSymbolAddress((void**)&WvT,     g_WvT);
    cudaGetSymbolAddress((void**)&WtT,     g_WtT);
    cudaGetSymbolAddress((void**)&WpT,     g_WpT);
    cudaGetSymbolAddress((void**)&logits,  g_logits);
    cudaGetSymbolAddress((void**)&pq,      g_pq);
    cudaGetSymbolAddress((void**)&pk,      g_pk);

    cudaFuncSetAttribute(gemm_h<false,false,false>, cudaFuncAttributeMaxDynamicSharedMemorySize, SMEM_GEMM);
    cudaFuncSetAttribute(gemm_h<true, false,true >, cudaFuncAttributeMaxDynamicSharedMemorySize, SMEM_GEMM);
    cudaFuncSetAttribute(gemm_h<false,true, true >, cudaFuncAttributeMaxDynamicSharedMemorySize, SMEM_GEMM);
    cudaFuncSetAttribute(logits2_kernel<false>, cudaFuncAttributeMaxDynamicSharedMemorySize, SMEM_LOGITS);
    cudaFuncSetAttribute(logits2_kernel<true >, cudaFuncAttributeMaxDynamicSharedMemorySize, SMEM_LOGITS);

    const dim3 ggrid(CC / BNH, MM / BMH);   // (8, 256)
    const dim3 tgrid(CC / 32, CC / 32, 5), tblk(32, 8);

    // #1 convert both activations
    f2h_all<<<dim3(MM * CC / 4 / 256, 2), 256>>>(x_q, xqh, x_kv, xkvh);
    // #2 transpose all 5 weights
    wtrans_all<<<tgrid, tblk>>>(Wq, Wk, Wv, Wt, Wp, WqT, WkT, WvT, WtT, WpT);
    // #3 queries = xq @ Wq + bq  (f32)
    gemm_h<false,false,false><<<ggrid, 256, SMEM_GEMM>>>(
        xqh, WqT, bq, nullptr, nullptr, queries, nullptr);
    // #4,#5 pooled_q
    logits2_kernel<false><<<MM / 128, 256, SMEM_LOGITS>>>(queries, Wqa, bqa, nullptr, logits);
    softmax_pool_kernel<<<NB * HH, 1024>>>(logits, queries, pq);
    // #6 keys = xkv @ Wk + bk  (f32)  <- profiled launch
    gemm_h<false,false,false><<<ggrid, 256, SMEM_GEMM>>>(
        xkvh, WkT, bk, nullptr, nullptr, keys, nullptr);
    // #7,#8 pooled_k (keys gated by pooled_q, folded into Wa_s)
    logits2_kernel<true><<<MM / 128, 256, SMEM_LOGITS>>>(keys, Wka, bka, pq, logits);
    softmax_pool_kernel<<<NB * HH, 1024>>>(logits, keys, pk);
    // #9 gated values = (xkv @ Wv + bv) * pk  (half)
    gemm_h<true,false,true><<<ggrid, 256, SMEM_GEMM>>>(
        xkvh, WvT, bv, pk, nullptr, nullptr, valgh);
    // #10 tsum = valg @ Wt + bt + queries  (half)
    gemm_h<false,true,true><<<ggrid, 256, SMEM_GEMM>>>(
        valgh, WtT, bt, nullptr, queries, nullptr, tsumh);
    // #11 out = tsum @ Wp + bp  (f32)
    gemm_h<false,false,false><<<ggrid, 256, SMEM_GEMM>>>(
        tsumh, WpT, bp, nullptr, nullptr, out, nullptr);
}